// round 1
// baseline (speedup 1.0000x reference)
#include <cuda_runtime.h>
#include <cuda_bf16.h>

// Problem constants
#define BATCH 2
#define HEADS 16
#define SEQ   4096
#define DIM   64
#define WIN   512
#define HALF  256
#define NFULL 15           // (4096-512)/256 + 1
#define P0    3840         // NFULL*HALF
#define ROWS_PER_BH 7936   // 15*512 + 256
#define BH    (BATCH*HEADS)

// Scratch for per-window attention outputs: [bh][7936][64] floats = ~130MB
__device__ float g_ws[(size_t)BH * ROWS_PER_BH * DIM];

#define KCHUNK 64

__global__ __launch_bounds__(128, 2)
void win_attn_kernel(const float* __restrict__ Q,
                     const float* __restrict__ K,
                     const float* __restrict__ V,
                     const float* __restrict__ scale_p)
{
    __shared__ float sk[KCHUNK * DIM];   // 16KB
    __shared__ float sv[KCHUNK * DIM];   // 16KB

    const int bh = blockIdx.y;
    const int t  = blockIdx.x;           // 0..61 tile id within bh

    int nkeys, key_start, row0;
    if (t < 60) {
        int w     = t >> 2;
        int qtile = t & 3;
        nkeys     = WIN;
        key_start = w * HALF;
        row0      = w * WIN + qtile * 128;
    } else {
        int qtile = t - 60;              // 0 or 1
        nkeys     = HALF;
        key_start = P0;
        row0      = NFULL * WIN + qtile * 128;
    }
    const int qtile_off = (t < 60) ? (t & 3) * 128 : (t - 60) * 128;
    const int q_global  = key_start + qtile_off + threadIdx.x;

    const size_t base = (size_t)bh * SEQ * DIM;

    // Load this thread's query row into registers
    float qreg[DIM];
    {
        const float4* qp = (const float4*)(Q + base + (size_t)q_global * DIM);
        #pragma unroll
        for (int i = 0; i < DIM / 4; i++) {
            float4 v = qp[i];
            qreg[4*i+0] = v.x; qreg[4*i+1] = v.y; qreg[4*i+2] = v.z; qreg[4*i+3] = v.w;
        }
    }
    const float scale = *scale_p;

    float acc[DIM];
    #pragma unroll
    for (int i = 0; i < DIM; i++) acc[i] = 0.0f;
    float denom = 0.0f;

    for (int c0 = 0; c0 < nkeys; c0 += KCHUNK) {
        __syncthreads();
        // Cooperative load of K/V chunk (coalesced float4)
        {
            const float4* kg = (const float4*)(K + base + (size_t)(key_start + c0) * DIM);
            const float4* vg = (const float4*)(V + base + (size_t)(key_start + c0) * DIM);
            #pragma unroll
            for (int i = 0; i < (KCHUNK * DIM / 4) / 128; i++) {
                int idx = threadIdx.x + i * 128;
                ((float4*)sk)[idx] = kg[idx];
                ((float4*)sv)[idx] = vg[idx];
            }
        }
        __syncthreads();

        #pragma unroll 4
        for (int j = 0; j < KCHUNK; j++) {
            const float4* kr = (const float4*)(sk + j * DIM);
            float s = 0.0f;
            #pragma unroll
            for (int i = 0; i < DIM / 4; i++) {
                float4 k4 = kr[i];
                s += qreg[4*i+0] * k4.x;
                s += qreg[4*i+1] * k4.y;
                s += qreg[4*i+2] * k4.z;
                s += qreg[4*i+3] * k4.w;
            }
            s *= scale;
            float p = 1.0f / (1.0f + __expf(-s));   // sigmoid
            denom += p;
            const float4* vr = (const float4*)(sv + j * DIM);
            #pragma unroll
            for (int i = 0; i < DIM / 4; i++) {
                float4 v4 = vr[i];
                acc[4*i+0] += p * v4.x;
                acc[4*i+1] += p * v4.y;
                acc[4*i+2] += p * v4.z;
                acc[4*i+3] += p * v4.w;
            }
        }
    }

    const float inv = 1.0f / denom;
    float4* orow = (float4*)(g_ws + ((size_t)bh * ROWS_PER_BH + row0 + threadIdx.x) * DIM);
    #pragma unroll
    for (int i = 0; i < DIM / 4; i++) {
        float4 o;
        o.x = acc[4*i+0] * inv;
        o.y = acc[4*i+1] * inv;
        o.z = acc[4*i+2] * inv;
        o.w = acc[4*i+3] * inv;
        orow[i] = o;
    }
}

// Blend kernel: out[bh][s][d] per the reference cross-fade.
__global__ __launch_bounds__(256)
void blend_kernel(float* __restrict__ out)
{
    const int D4 = DIM / 4;
    size_t tid = (size_t)blockIdx.x * blockDim.x + threadIdx.x;
    const size_t total = (size_t)BH * SEQ * D4;
    if (tid >= total) return;

    int d4 = (int)(tid % D4);
    size_t r = tid / D4;
    int s  = (int)(r % SEQ);
    int bh = (int)(r / SEQ);

    int k = s >> 8;           // s / 256
    int i = s & 255;          // s % 256
    float a = (float)i * (1.0f / 255.0f);

    const float4* ws = (const float4*)(g_ws + (size_t)bh * ROWS_PER_BH * DIM);

    float4 res;
    if (k == 0) {
        res = ws[(size_t)i * D4 + d4];
    } else if (k < NFULL) {
        // (1-a)*second_half(window k-1) + a*first_half(window k)
        float4 v0 = ws[(size_t)((k - 1) * WIN + HALF + i) * D4 + d4];
        float4 v1 = ws[(size_t)(k * WIN + i) * D4 + d4];
        res.x = (1.0f - a) * v0.x + a * v1.x;
        res.y = (1.0f - a) * v0.y + a * v1.y;
        res.z = (1.0f - a) * v0.z + a * v1.z;
        res.w = (1.0f - a) * v0.w + a * v1.w;
    } else {
        // tail: (1-a)*second_half(window 14) + a*partial
        float4 v0 = ws[(size_t)((NFULL - 1) * WIN + HALF + i) * D4 + d4];
        float4 v1 = ws[(size_t)(NFULL * WIN + i) * D4 + d4];
        res.x = (1.0f - a) * v0.x + a * v1.x;
        res.y = (1.0f - a) * v0.y + a * v1.y;
        res.z = (1.0f - a) * v0.z + a * v1.z;
        res.w = (1.0f - a) * v0.w + a * v1.w;
    }

    ((float4*)out)[tid] = res;
}

extern "C" void kernel_launch(void* const* d_in, const int* in_sizes, int n_in,
                              void* d_out, int out_size)
{
    const float* Q     = (const float*)d_in[0];
    const float* K     = (const float*)d_in[1];
    const float* V     = (const float*)d_in[2];
    const float* scale = (const float*)d_in[3];
    float* out = (float*)d_out;

    dim3 grid(62, BH);
    win_attn_kernel<<<grid, 128>>>(Q, K, V, scale);

    const size_t total4 = (size_t)BH * SEQ * (DIM / 4);
    int blocks = (int)((total4 + 255) / 256);
    blend_kernel<<<blocks, 256>>>(out);
}

// round 3
// speedup vs baseline: 3.6668x; 3.6668x over previous
#include <cuda_runtime.h>
#include <cstdint>

#define BATCH 2
#define HEADS 16
#define SEQ   4096
#define DIM   64
#define WIN   512
#define HALF  256
#define NFULL 15
#define P0    3840
#define ROWS_PER_BH 7936
#define BH    (BATCH*HEADS)

__device__ float g_ws[(size_t)BH * ROWS_PER_BH * DIM];   // per-window outputs

#define LDS_PAD 68                      // 64 + 4 floats: conflict-free fragment LDS
#define SM_K 0                          // [64][68]
#define SM_V (64*LDS_PAD)               // [64][68]
#define SM_P (2*64*LDS_PAD)             // [128][68]
#define SMEM_FLOATS (2*64*LDS_PAD + 128*LDS_PAD)
#define SMEM_BYTES  (SMEM_FLOATS*4)     // 69632

__device__ __forceinline__ uint32_t f2tf(float f) {
    uint32_t u;
    asm("cvt.rna.tf32.f32 %0, %1;" : "=r"(u) : "f"(f));
    return u;
}
__device__ __forceinline__ float sigmoid_fast(float x) {
    float t;
    asm("tanh.approx.f32 %0, %1;" : "=f"(t) : "f"(x * 0.5f));
    return fmaf(t, 0.5f, 0.5f);
}
__device__ __forceinline__ void mma_tf32(float c[4], const uint32_t a[4], uint32_t b0, uint32_t b1) {
    asm volatile(
        "mma.sync.aligned.m16n8k8.row.col.f32.tf32.tf32.f32 "
        "{%0,%1,%2,%3}, {%4,%5,%6,%7}, {%8,%9}, {%0,%1,%2,%3};"
        : "+f"(c[0]), "+f"(c[1]), "+f"(c[2]), "+f"(c[3])
        : "r"(a[0]), "r"(a[1]), "r"(a[2]), "r"(a[3]), "r"(b0), "r"(b1));
}

__global__ __launch_bounds__(256, 2)
void win_attn_mma(const float* __restrict__ Q,
                  const float* __restrict__ K,
                  const float* __restrict__ V,
                  const float* __restrict__ scale_p)
{
    extern __shared__ float sm[];
    const int tid  = threadIdx.x;
    const int lane = tid & 31;
    const int warp = tid >> 5;          // 0..7, owns q-rows [warp*16, warp*16+16)
    const int gid  = lane >> 2;         // 0..7
    const int tig  = lane & 3;          // 0..3

    const int bh = blockIdx.y;
    const int t  = blockIdx.x;

    int nkeys, key_start, row0, qoff;
    if (t < 60) {
        int w = t >> 2, qt = t & 3;
        nkeys = WIN; key_start = w * HALF; row0 = w * WIN + qt * 128; qoff = qt * 128;
    } else {
        int qt = t - 60;
        nkeys = HALF; key_start = P0; row0 = NFULL * WIN + qt * 128; qoff = qt * 128;
    }
    const int nchunks = nkeys >> 6;
    const size_t base = (size_t)bh * SEQ * DIM;
    const float scale = *scale_p;

    // ---- Q fragments (A of m16n8k8), scale folded in, kept in registers ----
    // a0:(gid, 8ks+tig) a1:(gid+8, 8ks+tig) a2:(gid, 8ks+tig+4) a3:(gid+8, 8ks+tig+4)
    uint32_t qa[8][4];
    {
        const float* q0 = Q + base + (size_t)(key_start + qoff + warp * 16 + gid) * DIM;
        const float* q1 = q0 + 8 * DIM;
        #pragma unroll
        for (int ks = 0; ks < 8; ks++) {
            qa[ks][0] = f2tf(__ldg(q0 + ks * 8 + tig)     * scale);
            qa[ks][1] = f2tf(__ldg(q1 + ks * 8 + tig)     * scale);
            qa[ks][2] = f2tf(__ldg(q0 + ks * 8 + tig + 4) * scale);
            qa[ks][3] = f2tf(__ldg(q1 + ks * 8 + tig + 4) * scale);
        }
    }

    float dacc[8][4];
    #pragma unroll
    for (int nt = 0; nt < 8; nt++)
        #pragma unroll
        for (int i = 0; i < 4; i++) dacc[nt][i] = 0.0f;
    float den0 = 0.0f, den1 = 0.0f;

    const int prow0 = warp * 16;        // this warp's slice of sP

    for (int c = 0; c < nchunks; c++) {
        const int k0 = key_start + c * 64;
        __syncthreads();                // protect sK/sV from previous chunk readers
        // ---- cooperative K/V chunk load -> padded smem, cvt to tf32 bits ----
        {
            const float4* kg = (const float4*)(K + base + (size_t)k0 * DIM);
            const float4* vg = (const float4*)(V + base + (size_t)k0 * DIM);
            #pragma unroll
            for (int i = 0; i < 4; i++) {
                int idx = tid + i * 256;            // 1024 float4s = 64x64
                int r = idx >> 4, c4 = idx & 15;
                float4 kv = kg[idx];
                float4 vv = vg[idx];
                uint4 ku = { f2tf(kv.x), f2tf(kv.y), f2tf(kv.z), f2tf(kv.w) };
                uint4 vu = { f2tf(vv.x), f2tf(vv.y), f2tf(vv.z), f2tf(vv.w) };
                *(uint4*)(sm + SM_K + r * LDS_PAD + c4 * 4) = ku;
                *(uint4*)(sm + SM_V + r * LDS_PAD + c4 * 4) = vu;
            }
        }
        __syncthreads();

        // ---- MMA1: S[16 x 64keys] = Qs . K^T ----
        float s[8][4];
        #pragma unroll
        for (int nt = 0; nt < 8; nt++)
            #pragma unroll
            for (int i = 0; i < 4; i++) s[nt][i] = 0.0f;

        const uint32_t* sKu = (const uint32_t*)(sm + SM_K);
        #pragma unroll
        for (int ks = 0; ks < 8; ks++) {
            #pragma unroll
            for (int nt = 0; nt < 8; nt++) {
                // B col-major: b0 = K[key nt*8+gid][dim 8ks+tig], b1 = dim+4
                const uint32_t* kp = sKu + (nt * 8 + gid) * LDS_PAD + ks * 8 + tig;
                mma_tf32(s[nt], qa[ks], kp[0], kp[4]);
            }
        }

        // ---- sigmoid + write P (warp-private slice of sP) + denom ----
        uint32_t* sPu = (uint32_t*)(sm + SM_P);
        #pragma unroll
        for (int nt = 0; nt < 8; nt++) {
            float p0 = sigmoid_fast(s[nt][0]);
            float p1 = sigmoid_fast(s[nt][1]);
            float p2 = sigmoid_fast(s[nt][2]);
            float p3 = sigmoid_fast(s[nt][3]);
            uint32_t u0 = f2tf(p0), u1 = f2tf(p1), u2 = f2tf(p2), u3 = f2tf(p3);
            // accumulate denom from the tf32-rounded values (consistency with MMA2)
            den0 += __uint_as_float(u0) + __uint_as_float(u1);
            den1 += __uint_as_float(u2) + __uint_as_float(u3);
            uint2 w0 = { u0, u1 }, w1 = { u2, u3 };
            *(uint2*)(sPu + (prow0 + gid)     * LDS_PAD + nt * 8 + 2 * tig) = w0;
            *(uint2*)(sPu + (prow0 + gid + 8) * LDS_PAD + nt * 8 + 2 * tig) = w1;
        }
        __syncwarp();

        // ---- MMA2: D[16 x 64dims] += P . V ----
        const uint32_t* sVu = (const uint32_t*)(sm + SM_V);
        #pragma unroll
        for (int ks = 0; ks < 8; ks++) {
            uint32_t pa[4];
            pa[0] = sPu[(prow0 + gid)     * LDS_PAD + ks * 8 + tig];
            pa[1] = sPu[(prow0 + gid + 8) * LDS_PAD + ks * 8 + tig];
            pa[2] = sPu[(prow0 + gid)     * LDS_PAD + ks * 8 + tig + 4];
            pa[3] = sPu[(prow0 + gid + 8) * LDS_PAD + ks * 8 + tig + 4];
            #pragma unroll
            for (int nt = 0; nt < 8; nt++) {
                // B col-major: b0 = V[key 8ks+tig][dim nt*8+gid], b1 = key+4
                uint32_t b0 = sVu[(ks * 8 + tig)     * LDS_PAD + nt * 8 + gid];
                uint32_t b1 = sVu[(ks * 8 + tig + 4) * LDS_PAD + nt * 8 + gid];
                mma_tf32(dacc[nt], pa, b0, b1);
            }
        }
    }

    // ---- denom reduce within quad (lanes sharing the same rows) ----
    den0 += __shfl_xor_sync(0xFFFFFFFF, den0, 1);
    den0 += __shfl_xor_sync(0xFFFFFFFF, den0, 2);
    den1 += __shfl_xor_sync(0xFFFFFFFF, den1, 1);
    den1 += __shfl_xor_sync(0xFFFFFFFF, den1, 2);
    const float inv0 = 1.0f / den0;
    const float inv1 = 1.0f / den1;

    // ---- epilogue: D/denom -> g_ws ----
    {
        float* o0 = g_ws + ((size_t)bh * ROWS_PER_BH + row0 + warp * 16 + gid) * DIM;
        float* o1 = o0 + 8 * DIM;
        #pragma unroll
        for (int nt = 0; nt < 8; nt++) {
            float2 r0 = { dacc[nt][0] * inv0, dacc[nt][1] * inv0 };
            float2 r1 = { dacc[nt][2] * inv1, dacc[nt][3] * inv1 };
            *(float2*)(o0 + nt * 8 + 2 * tig) = r0;
            *(float2*)(o1 + nt * 8 + 2 * tig) = r1;
        }
    }
}

// ---------------- Blend ----------------
__global__ __launch_bounds__(256)
void blend_kernel(float* __restrict__ out)
{
    const int D4 = DIM / 4;
    size_t tid = (size_t)blockIdx.x * blockDim.x + threadIdx.x;
    const size_t total = (size_t)BH * SEQ * D4;
    if (tid >= total) return;

    int d4 = (int)(tid % D4);
    size_t r = tid / D4;
    int s  = (int)(r % SEQ);
    int bh = (int)(r / SEQ);

    int k = s >> 8;
    int i = s & 255;
    float a = (float)i * (1.0f / 255.0f);

    const float4* ws = (const float4*)(g_ws + (size_t)bh * ROWS_PER_BH * DIM);

    float4 res;
    if (k == 0) {
        res = ws[(size_t)i * D4 + d4];
    } else if (k < NFULL) {
        float4 v0 = ws[(size_t)((k - 1) * WIN + HALF + i) * D4 + d4];
        float4 v1 = ws[(size_t)(k * WIN + i) * D4 + d4];
        res.x = (1.0f - a) * v0.x + a * v1.x;
        res.y = (1.0f - a) * v0.y + a * v1.y;
        res.z = (1.0f - a) * v0.z + a * v1.z;
        res.w = (1.0f - a) * v0.w + a * v1.w;
    } else {
        float4 v0 = ws[(size_t)((NFULL - 1) * WIN + HALF + i) * D4 + d4];
        float4 v1 = ws[(size_t)(NFULL * WIN + i) * D4 + d4];
        res.x = (1.0f - a) * v0.x + a * v1.x;
        res.y = (1.0f - a) * v0.y + a * v1.y;
        res.z = (1.0f - a) * v0.z + a * v1.z;
        res.w = (1.0f - a) * v0.w + a * v1.w;
    }
    ((float4*)out)[tid] = res;
}

extern "C" void kernel_launch(void* const* d_in, const int* in_sizes, int n_in,
                              void* d_out, int out_size)
{
    const float* Q     = (const float*)d_in[0];
    const float* K     = (const float*)d_in[1];
    const float* V     = (const float*)d_in[2];
    const float* scale = (const float*)d_in[3];
    float* out = (float*)d_out;

    static bool attr_set = false;
    if (!attr_set) {
        cudaFuncSetAttribute(win_attn_mma, cudaFuncAttributeMaxDynamicSharedMemorySize, SMEM_BYTES);
        attr_set = true;
    }

    dim3 grid(62, BH);
    win_attn_mma<<<grid, 256, SMEM_BYTES>>>(Q, K, V, scale);

    const size_t total4 = (size_t)BH * SEQ * (DIM / 4);
    int blocks = (int)((total4 + 255) / 256);
    blend_kernel<<<blocks, 256>>>(out);
}

// round 4
// speedup vs baseline: 6.0229x; 1.6426x over previous
#include <cuda_runtime.h>
#include <cuda_fp16.h>
#include <cstdint>

#define BATCH 2
#define HEADS 16
#define SEQ   4096
#define DIM   64
#define WIN   512
#define HALF  256
#define NFULL 15
#define P0    3840
#define ROWS_PER_BH 7936
#define BH    (BATCH*HEADS)

__device__ float g_ws[(size_t)BH * ROWS_PER_BH * DIM];   // per-window outputs

#define KSTRIDE 72   // halves per smem row (64 data + 8 pad) -> conflict-free frags

__device__ __forceinline__ uint32_t pack_h2(float a, float b) {
    __half2 h = __floats2half2_rn(a, b);
    return *(uint32_t*)&h;
}
__device__ __forceinline__ float sigmoid_fast(float x) {
    float t;
    asm("tanh.approx.f32 %0, %1;" : "=f"(t) : "f"(x * 0.5f));
    return fmaf(t, 0.5f, 0.5f);
}
__device__ __forceinline__ void mma_f16(float c[4], const uint32_t a[4], uint32_t b0, uint32_t b1) {
    asm volatile(
        "mma.sync.aligned.m16n8k16.row.col.f32.f16.f16.f32 "
        "{%0,%1,%2,%3}, {%4,%5,%6,%7}, {%8,%9}, {%0,%1,%2,%3};"
        : "+f"(c[0]), "+f"(c[1]), "+f"(c[2]), "+f"(c[3])
        : "r"(a[0]), "r"(a[1]), "r"(a[2]), "r"(a[3]), "r"(b0), "r"(b1));
}

__global__ __launch_bounds__(256, 2)
void win_attn_h(const float* __restrict__ Q,
                const float* __restrict__ K,
                const float* __restrict__ V,
                const float* __restrict__ scale_p)
{
    __shared__ __align__(16) __half smK [64 * KSTRIDE];  // [key][dim]
    __shared__ __align__(16) __half smVT[64 * KSTRIDE];  // [dim][key]

    const int tid  = threadIdx.x;
    const int lane = tid & 31;
    const int warp = tid >> 5;          // 0..7, owns q-rows [warp*16, warp*16+16)
    const int gid  = lane >> 2;         // 0..7
    const int tig  = lane & 3;          // 0..3

    const int bh = blockIdx.y;
    const int t  = blockIdx.x;

    int nkeys, key_start, row0, qoff;
    if (t < 60) {
        int w = t >> 2, qt = t & 3;
        nkeys = WIN; key_start = w * HALF; row0 = w * WIN + qt * 128; qoff = qt * 128;
    } else {
        int qt = t - 60;
        nkeys = HALF; key_start = P0; row0 = NFULL * WIN + qt * 128; qoff = qt * 128;
    }
    const int nchunks = nkeys >> 6;
    const size_t base = (size_t)bh * SEQ * DIM;
    const float scale = *scale_p;

    // ---- Q fragments for m16n8k16 (A), fp16, scale folded in ----
    // qa[ks][0]={Q[gid][16ks+2tig..+1]}, [1]=row gid+8, [2]=cols+8, [3]=row+8,cols+8
    uint32_t qa[4][4];
    {
        const float* q0 = Q + base + (size_t)(key_start + qoff + warp * 16 + gid) * DIM;
        const float* q1 = q0 + 8 * DIM;
        #pragma unroll
        for (int ks = 0; ks < 4; ks++) {
            float2 v;
            v = *(const float2*)(q0 + ks * 16 + 2 * tig);
            qa[ks][0] = pack_h2(v.x * scale, v.y * scale);
            v = *(const float2*)(q1 + ks * 16 + 2 * tig);
            qa[ks][1] = pack_h2(v.x * scale, v.y * scale);
            v = *(const float2*)(q0 + ks * 16 + 2 * tig + 8);
            qa[ks][2] = pack_h2(v.x * scale, v.y * scale);
            v = *(const float2*)(q1 + ks * 16 + 2 * tig + 8);
            qa[ks][3] = pack_h2(v.x * scale, v.y * scale);
        }
    }

    float dacc[8][4];
    #pragma unroll
    for (int nt = 0; nt < 8; nt++)
        #pragma unroll
        for (int i = 0; i < 4; i++) dacc[nt][i] = 0.0f;
    float den0 = 0.0f, den1 = 0.0f;

    const uint32_t* sKu = (const uint32_t*)smK;
    const uint32_t* sVu = (const uint32_t*)smVT;
    const int brow = gid * (KSTRIDE / 2) + tig;   // base uint-index offset for gid/tig

    // prefetch chunk 0
    float4 kreg[4], vreg[4];
    {
        const float4* kg = (const float4*)(K + base + (size_t)key_start * DIM);
        const float4* vg = (const float4*)(V + base + (size_t)key_start * DIM);
        #pragma unroll
        for (int i = 0; i < 4; i++) { kreg[i] = kg[tid + i * 256]; vreg[i] = vg[tid + i * 256]; }
    }

    for (int c = 0; c < nchunks; c++) {
        if (c > 0) __syncthreads();      // all warps done reading smem of chunk c-1
        // ---- store staged K (fp16, [key][dim]) and V^T (fp16, [dim][key]) ----
        #pragma unroll
        for (int i = 0; i < 4; i++) {
            int idx = tid + i * 256;
            int r = idx >> 4, c4 = idx & 15;
            uint2 kk = { pack_h2(kreg[i].x, kreg[i].y), pack_h2(kreg[i].z, kreg[i].w) };
            *(uint2*)((char*)smK + r * (KSTRIDE * 2) + c4 * 8) = kk;
            smVT[(4 * c4 + 0) * KSTRIDE + r] = __float2half_rn(vreg[i].x);
            smVT[(4 * c4 + 1) * KSTRIDE + r] = __float2half_rn(vreg[i].y);
            smVT[(4 * c4 + 2) * KSTRIDE + r] = __float2half_rn(vreg[i].z);
            smVT[(4 * c4 + 3) * KSTRIDE + r] = __float2half_rn(vreg[i].w);
        }
        __syncthreads();

        // prefetch next chunk (overlaps the MMAs below)
        if (c + 1 < nchunks) {
            const int k1 = key_start + (c + 1) * 64;
            const float4* kg = (const float4*)(K + base + (size_t)k1 * DIM);
            const float4* vg = (const float4*)(V + base + (size_t)k1 * DIM);
            #pragma unroll
            for (int i = 0; i < 4; i++) { kreg[i] = kg[tid + i * 256]; vreg[i] = vg[tid + i * 256]; }
        }

        // ---- MMA1 per n-tile + sigmoid -> register-resident P fragments ----
        uint32_t pa[4][4];
        #pragma unroll
        for (int nt = 0; nt < 8; nt++) {
            float sl[4] = {0.0f, 0.0f, 0.0f, 0.0f};
            const int rb = nt * 8 * (KSTRIDE / 2) + brow;
            #pragma unroll
            for (int ks = 0; ks < 4; ks++) {
                uint32_t b0 = sKu[rb + 8 * ks];
                uint32_t b1 = sKu[rb + 8 * ks + 4];
                mma_f16(sl, qa[ks], b0, b1);
            }
            float p0 = sigmoid_fast(sl[0]);
            float p1 = sigmoid_fast(sl[1]);
            float p2 = sigmoid_fast(sl[2]);
            float p3 = sigmoid_fast(sl[3]);
            uint32_t u01 = pack_h2(p0, p1);
            uint32_t u23 = pack_h2(p2, p3);
            // denom from the fp16-rounded values (consistency with MMA2 numerator)
            float2 f01 = __half22float2(*(__half2*)&u01);
            float2 f23 = __half22float2(*(__half2*)&u23);
            den0 += f01.x + f01.y;
            den1 += f23.x + f23.y;
            int kc = nt >> 1, hi = (nt & 1) * 2;
            pa[kc][hi]     = u01;
            pa[kc][hi + 1] = u23;
        }

        // ---- MMA2: D += P . V  (A = pa, B from V^T tile) ----
        #pragma unroll
        for (int kc = 0; kc < 4; kc++) {
            #pragma unroll
            for (int nt = 0; nt < 8; nt++) {
                const int rb = nt * 8 * (KSTRIDE / 2) + brow;
                uint32_t b0 = sVu[rb + 8 * kc];
                uint32_t b1 = sVu[rb + 8 * kc + 4];
                mma_f16(dacc[nt], pa[kc], b0, b1);
            }
        }
    }

    // ---- denom reduce within quad (lanes sharing the same rows) ----
    den0 += __shfl_xor_sync(0xFFFFFFFF, den0, 1);
    den0 += __shfl_xor_sync(0xFFFFFFFF, den0, 2);
    den1 += __shfl_xor_sync(0xFFFFFFFF, den1, 1);
    den1 += __shfl_xor_sync(0xFFFFFFFF, den1, 2);
    const float inv0 = 1.0f / den0;
    const float inv1 = 1.0f / den1;

    // ---- epilogue: D/denom -> g_ws ----
    {
        float* o0 = g_ws + ((size_t)bh * ROWS_PER_BH + row0 + warp * 16 + gid) * DIM;
        float* o1 = o0 + 8 * DIM;
        #pragma unroll
        for (int nt = 0; nt < 8; nt++) {
            float2 r0 = { dacc[nt][0] * inv0, dacc[nt][1] * inv0 };
            float2 r1 = { dacc[nt][2] * inv1, dacc[nt][3] * inv1 };
            *(float2*)(o0 + nt * 8 + 2 * tig) = r0;
            *(float2*)(o1 + nt * 8 + 2 * tig) = r1;
        }
    }
}

// ---------------- Blend ----------------
__global__ __launch_bounds__(256)
void blend_kernel(float* __restrict__ out)
{
    const int D4 = DIM / 4;
    size_t tid = (size_t)blockIdx.x * blockDim.x + threadIdx.x;
    const size_t total = (size_t)BH * SEQ * D4;
    if (tid >= total) return;

    int d4 = (int)(tid % D4);
    size_t r = tid / D4;
    int s  = (int)(r % SEQ);
    int bh = (int)(r / SEQ);

    int k = s >> 8;
    int i = s & 255;
    float a = (float)i * (1.0f / 255.0f);

    const float4* ws = (const float4*)(g_ws + (size_t)bh * ROWS_PER_BH * DIM);

    float4 res;
    if (k == 0) {
        res = ws[(size_t)i * D4 + d4];
    } else if (k < NFULL) {
        float4 v0 = ws[(size_t)((k - 1) * WIN + HALF + i) * D4 + d4];
        float4 v1 = ws[(size_t)(k * WIN + i) * D4 + d4];
        res.x = (1.0f - a) * v0.x + a * v1.x;
        res.y = (1.0f - a) * v0.y + a * v1.y;
        res.z = (1.0f - a) * v0.z + a * v1.z;
        res.w = (1.0f - a) * v0.w + a * v1.w;
    } else {
        float4 v0 = ws[(size_t)((NFULL - 1) * WIN + HALF + i) * D4 + d4];
        float4 v1 = ws[(size_t)(NFULL * WIN + i) * D4 + d4];
        res.x = (1.0f - a) * v0.x + a * v1.x;
        res.y = (1.0f - a) * v0.y + a * v1.y;
        res.z = (1.0f - a) * v0.z + a * v1.z;
        res.w = (1.0f - a) * v0.w + a * v1.w;
    }
    ((float4*)out)[tid] = res;
}

extern "C" void kernel_launch(void* const* d_in, const int* in_sizes, int n_in,
                              void* d_out, int out_size)
{
    const float* Q     = (const float*)d_in[0];
    const float* K     = (const float*)d_in[1];
    const float* V     = (const float*)d_in[2];
    const float* scale = (const float*)d_in[3];
    float* out = (float*)d_out;

    dim3 grid(62, BH);
    win_attn_h<<<grid, 256>>>(Q, K, V, scale);

    const size_t total4 = (size_t)BH * SEQ * (DIM / 4);
    int blocks = (int)((total4 + 255) / 256);
    blend_kernel<<<blocks, 256>>>(out);
}